// round 1
// baseline (speedup 1.0000x reference)
#include <cuda_runtime.h>

// torch RReLU eval-mode negative slope = (1/8 + 1/3)/2 = 11/48
#define RRELU_SLOPE 0.22916666666666666f

// Shared layout (floats):
//   W1 [96*64] | W2 [64*64] | W3 [64*32] | b1[64] | b2[64] | b3[32] | hstage[256*65]
static constexpr int W1_F = 96 * 64;
static constexpr int W2_F = 64 * 64;
static constexpr int W3_F = 64 * 32;
static constexpr int HPAD = 65;                       // 64 + 1 pad -> conflict-free (tid+k)%32
static constexpr int SMEM_FLOATS = W1_F + W2_F + W3_F + 64 + 64 + 32 + 256 * HPAD;
static constexpr size_t SMEM_BYTES = (size_t)SMEM_FLOATS * sizeof(float);

// FMA a broadcast scalar x against one weight row (NC outputs) into acc, via float4 LDS.
template <int NC>
__device__ __forceinline__ void fma_row(float xv, const float* __restrict__ wrow,
                                        float (&acc)[NC]) {
    const float4* wr = reinterpret_cast<const float4*>(wrow);
#pragma unroll
    for (int j = 0; j < NC / 4; ++j) {
        float4 w = wr[j];
        acc[4 * j + 0] = fmaf(xv, w.x, acc[4 * j + 0]);
        acc[4 * j + 1] = fmaf(xv, w.y, acc[4 * j + 1]);
        acc[4 * j + 2] = fmaf(xv, w.z, acc[4 * j + 2]);
        acc[4 * j + 3] = fmaf(xv, w.w, acc[4 * j + 3]);
    }
}

__device__ __forceinline__ float rrelu(float v) {
    return (v >= 0.0f) ? v : v * RRELU_SLOPE;
}

__global__ void __launch_bounds__(256, 1)
edge_mlp_kernel(const float* __restrict__ bonds,
                const int*   __restrict__ ia1,
                const int*   __restrict__ ia2,
                const float* __restrict__ atoms,
                const float* __restrict__ W1, const float* __restrict__ B1,
                const float* __restrict__ W2, const float* __restrict__ B2,
                const float* __restrict__ W3, const float* __restrict__ B3,
                float* __restrict__ out, int n_bonds) {
    extern __shared__ float smem[];
    float* w1s = smem;
    float* w2s = w1s + W1_F;
    float* w3s = w2s + W2_F;
    float* b1s = w3s + W3_F;
    float* b2s = b1s + 64;
    float* b3s = b2s + 64;
    float* hst = b3s + 32;

    const int tid = threadIdx.x;

    // Cooperative weight/bias stage into shared (one-time per block).
    for (int i = tid; i < W1_F; i += 256) w1s[i] = W1[i];
    for (int i = tid; i < W2_F; i += 256) w2s[i] = W2[i];
    for (int i = tid; i < W3_F; i += 256) w3s[i] = W3[i];
    if (tid < 64) { b1s[tid] = B1[tid]; b2s[tid] = B2[tid]; }
    if (tid < 32) { b3s[tid] = B3[tid]; }
    __syncthreads();
    // After this point each thread only touches its private hstage row -> no more barriers.

    const int b = blockIdx.x * 256 + tid;
    if (b >= n_bonds) return;

    const float4* a1p = reinterpret_cast<const float4*>(atoms + (size_t)ia1[b] * 32);
    const float4* a2p = reinterpret_cast<const float4*>(atoms + (size_t)ia2[b] * 32);
    const float4* bp  = reinterpret_cast<const float4*>(bonds + (size_t)b * 32);

    float* myh = hst + tid * HPAD;     // private 64-float stage, padded stride

    // -------- Layer 1: x[96] @ W1[96,64] + b1, RReLU --------
    float acc[64];
#pragma unroll
    for (int j = 0; j < 64; ++j) acc[j] = b1s[j];

#pragma unroll 1
    for (int q = 0; q < 8; ++q) {      // atom-1 features: k = 0..31
        float4 x = a1p[q];
        const int k = 4 * q;
        fma_row<64>(x.x, w1s + (k + 0) * 64, acc);
        fma_row<64>(x.y, w1s + (k + 1) * 64, acc);
        fma_row<64>(x.z, w1s + (k + 2) * 64, acc);
        fma_row<64>(x.w, w1s + (k + 3) * 64, acc);
    }
#pragma unroll 1
    for (int q = 0; q < 8; ++q) {      // atom-2 features: k = 32..63
        float4 x = a2p[q];
        const int k = 32 + 4 * q;
        fma_row<64>(x.x, w1s + (k + 0) * 64, acc);
        fma_row<64>(x.y, w1s + (k + 1) * 64, acc);
        fma_row<64>(x.z, w1s + (k + 2) * 64, acc);
        fma_row<64>(x.w, w1s + (k + 3) * 64, acc);
    }
#pragma unroll 1
    for (int q = 0; q < 8; ++q) {      // bond features: k = 64..95
        float4 x = bp[q];
        const int k = 64 + 4 * q;
        fma_row<64>(x.x, w1s + (k + 0) * 64, acc);
        fma_row<64>(x.y, w1s + (k + 1) * 64, acc);
        fma_row<64>(x.z, w1s + (k + 2) * 64, acc);
        fma_row<64>(x.w, w1s + (k + 3) * 64, acc);
    }

#pragma unroll
    for (int j = 0; j < 64; ++j) myh[j] = rrelu(acc[j]);

    // -------- Layer 2: h1[64] @ W2[64,64] + b2, RReLU --------
    float acc2[64];
#pragma unroll
    for (int j = 0; j < 64; ++j) acc2[j] = b2s[j];

#pragma unroll 1
    for (int k = 0; k < 64; ++k) {
        float xv = myh[k];             // conflict-free broadcast-free private read
        fma_row<64>(xv, w2s + k * 64, acc2);
    }

#pragma unroll
    for (int j = 0; j < 64; ++j) myh[j] = rrelu(acc2[j]);

    // -------- Layer 3: h2[64] @ W3[64,32] + b3 --------
    float acc3[32];
#pragma unroll
    for (int j = 0; j < 32; ++j) acc3[j] = b3s[j];

#pragma unroll 1
    for (int k = 0; k < 64; ++k) {
        float xv = myh[k];
        fma_row<32>(xv, w3s + k * 32, acc3);
    }

    float4* op = reinterpret_cast<float4*>(out + (size_t)b * 32);
#pragma unroll
    for (int j = 0; j < 8; ++j) {
        op[j] = make_float4(acc3[4 * j + 0], acc3[4 * j + 1],
                            acc3[4 * j + 2], acc3[4 * j + 3]);
    }
}

extern "C" void kernel_launch(void* const* d_in, const int* in_sizes, int n_in,
                              void* d_out, int out_size) {
    const float* bonds = (const float*)d_in[0];
    const int*   ia1   = (const int*)  d_in[1];
    const int*   ia2   = (const int*)  d_in[2];
    const float* atoms = (const float*)d_in[3];
    const float* W1    = (const float*)d_in[4];
    const float* B1    = (const float*)d_in[5];
    const float* W2    = (const float*)d_in[6];
    const float* B2    = (const float*)d_in[7];
    const float* W3    = (const float*)d_in[8];
    const float* B3    = (const float*)d_in[9];
    float*       out   = (float*)d_out;

    const int n_bonds = in_sizes[1];   // bond_atom_1 element count = N_BONDS

    // >48KB dynamic shared requires explicit opt-in (idempotent, capture-safe).
    cudaFuncSetAttribute(edge_mlp_kernel,
                         cudaFuncAttributeMaxDynamicSharedMemorySize,
                         (int)SMEM_BYTES);

    const int grid = (n_bonds + 255) / 256;
    edge_mlp_kernel<<<grid, 256, SMEM_BYTES>>>(bonds, ia1, ia2, atoms,
                                               W1, B1, W2, B2, W3, B3,
                                               out, n_bonds);
}

// round 7
// speedup vs baseline: 1.4832x; 1.4832x over previous
#include <cuda_runtime.h>
#include <cstdint>

#define RRELU_SLOPE 0.22916666666666666f

using ull = unsigned long long;

static constexpr int BM      = 96;     // bonds per block
static constexpr int THREADS = 256;    // 8 warps
static constexpr int XS      = 97;     // x-tile stride   (odd -> conflict-free scalar)
static constexpr int HS      = 65;     // h-tile stride
static constexpr int OS      = 33;     // out-stage stride

static constexpr int W1_F = 96 * 64;
static constexpr int W2_F = 64 * 64;
static constexpr int W3_F = 64 * 32;
static constexpr int A_F  = BM * XS;   // x tile, later h2 tile (stride HS), 9312 floats
static constexpr int B_F  = BM * HS;   // h1 tile, later out-stage (stride OS), 6240 floats
static constexpr int SMEM_FLOATS = W1_F + W2_F + W3_F + 64 + 64 + 32 + A_F + B_F + 2 * BM;
static constexpr size_t SMEM_BYTES = (size_t)SMEM_FLOATS * sizeof(float);

// packed fp32x2 FMA (SASS FFMA2): d = a*b + c, per 32-bit lane. Bitwise == two fmaf.
__device__ __forceinline__ ull ffma2(ull a, ull b, ull c) {
    ull d;
    asm("fma.rn.f32x2 %0, %1, %2, %3;" : "=l"(d) : "l"(a), "l"(b), "l"(c));
    return d;
}
__device__ __forceinline__ ull pack2(float x) {   // (x, x)
    ull d;
    asm("mov.b64 %0, {%1, %1};" : "=l"(d) : "r"(__float_as_uint(x)));
    return d;
}
__device__ __forceinline__ void unpack2(ull v, float& lo, float& hi) {
    uint32_t a, b;
    asm("mov.b64 {%0, %1}, %2;" : "=r"(a), "=r"(b) : "l"(v));
    lo = __uint_as_float(a);
    hi = __uint_as_float(b);
}
__device__ __forceinline__ float rrelu(float v) {
    return (v >= 0.0f) ? v : v * RRELU_SLOPE;
}

__global__ void __launch_bounds__(THREADS, 2)
edge_mlp_kernel(const float* __restrict__ bonds,
                const int*   __restrict__ ia1,
                const int*   __restrict__ ia2,
                const float* __restrict__ atoms,
                const float* __restrict__ W1, const float* __restrict__ B1,
                const float* __restrict__ W2, const float* __restrict__ B2,
                const float* __restrict__ W3, const float* __restrict__ B3,
                float* __restrict__ out, int n_bonds) {
    extern __shared__ float smem[];
    float* w1s = smem;
    float* w2s = w1s + W1_F;
    float* w3s = w2s + W2_F;
    float* b1s = w3s + W3_F;
    float* b2s = b1s + 64;
    float* b3s = b2s + 64;
    float* At  = b3s + 32;            // [BM][XS] x tile; reused as h2 [BM][HS]
    float* Bt  = At + A_F;            // [BM][HS] h1 tile; reused as out-stage [BM][OS]
    int*   idxs = (int*)(Bt + B_F);   // [2*BM]

    const int tid   = threadIdx.x;
    const int lane  = tid & 31;
    const int warp  = tid >> 5;
    const int gbase = blockIdx.x * BM;

    // ---- stage gather indices (clamped for tail block) ----
    if (tid < BM) {
        int g = gbase + tid;
        idxs[tid] = (g < n_bonds) ? ia1[g] : 0;
    } else if (tid < 2 * BM) {
        int t = tid - BM, g = gbase + t;
        idxs[BM + t] = (g < n_bonds) ? ia2[g] : 0;
    }

    // ---- stage weights / biases (cooperative, once per block) ----
    for (int i = tid; i < W1_F; i += THREADS) w1s[i] = W1[i];
    for (int i = tid; i < W2_F; i += THREADS) w2s[i] = W2[i];
    for (int i = tid; i < W3_F; i += THREADS) w3s[i] = W3[i];
    if (tid < 64) { b1s[tid] = B1[tid]; b2s[tid] = B2[tid]; }
    if (tid < 32) { b3s[tid] = B3[tid]; }
    __syncthreads();

    // ---- gather x = [a1 | a2 | bond] into At[bond][96], stride XS ----
    {
        const float4* atoms4 = (const float4*)atoms;
        const float4* bonds4 = (const float4*)bonds;
#pragma unroll
        for (int it = 0; it < 3; ++it) {          // a1 features 0..31
            int idx = tid + it * THREADS;         // BM*8 = 768 work items
            int b = idx >> 3, c = idx & 7;
            float4 v = atoms4[(size_t)idxs[b] * 8 + c];
            float* d = At + b * XS + 4 * c;
            d[0] = v.x; d[1] = v.y; d[2] = v.z; d[3] = v.w;
        }
#pragma unroll
        for (int it = 0; it < 3; ++it) {          // a2 features 32..63
            int idx = tid + it * THREADS;
            int b = idx >> 3, c = idx & 7;
            float4 v = atoms4[(size_t)idxs[BM + b] * 8 + c];
            float* d = At + b * XS + 32 + 4 * c;
            d[0] = v.x; d[1] = v.y; d[2] = v.z; d[3] = v.w;
        }
#pragma unroll
        for (int it = 0; it < 3; ++it) {          // bond features 64..95
            int idx = tid + it * THREADS;
            int b = idx >> 3, c = idx & 7;
            int g = gbase + b;
            if (g >= n_bonds) g = gbase;          // safe clamp (block start always valid)
            float4 v = bonds4[(size_t)g * 8 + c];
            float* d = At + b * XS + 64 + 4 * c;
            d[0] = v.x; d[1] = v.y; d[2] = v.z; d[3] = v.w;
        }
    }
    __syncthreads();

    // thread tile: bonds {lane, lane+32, lane+64}, outputs {8*warp .. 8*warp+7}
    // ---- layer 1: x[96] @ W1 -> h1[64], RReLU ----
    {
        ull acc[3][4];
        {
            const ulonglong2* bb = (const ulonglong2*)(b1s + 8 * warp);
            ulonglong2 p0 = bb[0], p1 = bb[1];
#pragma unroll
            for (int i = 0; i < 3; ++i) {
                acc[i][0] = p0.x; acc[i][1] = p0.y;
                acc[i][2] = p1.x; acc[i][3] = p1.y;
            }
        }
        const float* x0 = At + lane * XS;
        const float* x1 = x0 + 32 * XS;
        const float* x2 = x1 + 32 * XS;
        const float* wr = w1s + 8 * warp;
#pragma unroll 4
        for (int k = 0; k < 96; ++k) {
            ulonglong2 wA = *(const ulonglong2*)(wr);
            ulonglong2 wB = *(const ulonglong2*)(wr + 4);
            wr += 64;
            ull xp0 = pack2(x0[k]), xp1 = pack2(x1[k]), xp2 = pack2(x2[k]);
            acc[0][0] = ffma2(xp0, wA.x, acc[0][0]);
            acc[0][1] = ffma2(xp0, wA.y, acc[0][1]);
            acc[0][2] = ffma2(xp0, wB.x, acc[0][2]);
            acc[0][3] = ffma2(xp0, wB.y, acc[0][3]);
            acc[1][0] = ffma2(xp1, wA.x, acc[1][0]);
            acc[1][1] = ffma2(xp1, wA.y, acc[1][1]);
            acc[1][2] = ffma2(xp1, wB.x, acc[1][2]);
            acc[1][3] = ffma2(xp1, wB.y, acc[1][3]);
            acc[2][0] = ffma2(xp2, wA.x, acc[2][0]);
            acc[2][1] = ffma2(xp2, wA.y, acc[2][1]);
            acc[2][2] = ffma2(xp2, wB.x, acc[2][2]);
            acc[2][3] = ffma2(xp2, wB.y, acc[2][3]);
        }
#pragma unroll
        for (int i = 0; i < 3; ++i) {
            float* hd = Bt + (lane + 32 * i) * HS + 8 * warp;
#pragma unroll
            for (int p = 0; p < 4; ++p) {
                float lo, hi;
                unpack2(acc[i][p], lo, hi);
                hd[2 * p]     = rrelu(lo);
                hd[2 * p + 1] = rrelu(hi);
            }
        }
    }
    __syncthreads();

    // ---- layer 2: h1[64] @ W2 -> h2[64], RReLU (h1 in Bt, h2 into At) ----
    {
        ull acc[3][4];
        {
            const ulonglong2* bb = (const ulonglong2*)(b2s + 8 * warp);
            ulonglong2 p0 = bb[0], p1 = bb[1];
#pragma unroll
            for (int i = 0; i < 3; ++i) {
                acc[i][0] = p0.x; acc[i][1] = p0.y;
                acc[i][2] = p1.x; acc[i][3] = p1.y;
            }
        }
        const float* x0 = Bt + lane * HS;
        const float* x1 = x0 + 32 * HS;
        const float* x2 = x1 + 32 * HS;
        const float* wr = w2s + 8 * warp;
#pragma unroll 4
        for (int k = 0; k < 64; ++k) {
            ulonglong2 wA = *(const ulonglong2*)(wr);
            ulonglong2 wB = *(const ulonglong2*)(wr + 4);
            wr += 64;
            ull xp0 = pack2(x0[k]), xp1 = pack2(x1[k]), xp2 = pack2(x2[k]);
            acc[0][0] = ffma2(xp0, wA.x, acc[0][0]);
            acc[0][1] = ffma2(xp0, wA.y, acc[0][1]);
            acc[0][2] = ffma2(xp0, wB.x, acc[0][2]);
            acc[0][3] = ffma2(xp0, wB.y, acc[0][3]);
            acc[1][0] = ffma2(xp1, wA.x, acc[1][0]);
            acc[1][1] = ffma2(xp1, wA.y, acc[1][1]);
            acc[1][2] = ffma2(xp1, wB.x, acc[1][2]);
            acc[1][3] = ffma2(xp1, wB.y, acc[1][3]);
            acc[2][0] = ffma2(xp2, wA.x, acc[2][0]);
            acc[2][1] = ffma2(xp2, wA.y, acc[2][1]);
            acc[2][2] = ffma2(xp2, wB.x, acc[2][2]);
            acc[2][3] = ffma2(xp2, wB.y, acc[2][3]);
        }
        __syncthreads();   // all h1 reads done before At (x) is overwritten with h2
#pragma unroll
        for (int i = 0; i < 3; ++i) {
            float* hd = At + (lane + 32 * i) * HS + 8 * warp;
#pragma unroll
            for (int p = 0; p < 4; ++p) {
                float lo, hi;
                unpack2(acc[i][p], lo, hi);
                hd[2 * p]     = rrelu(lo);
                hd[2 * p + 1] = rrelu(hi);
            }
        }
    }
    __syncthreads();

    // ---- layer 3: h2[64] @ W3 -> y[32]  (h2 in At; outputs {4*warp..4*warp+3}) ----
    {
        ull acc[3][2];
        {
            ulonglong2 p0 = *(const ulonglong2*)(b3s + 4 * warp);
#pragma unroll
            for (int i = 0; i < 3; ++i) { acc[i][0] = p0.x; acc[i][1] = p0.y; }
        }
        const float* x0 = At + lane * HS;
        const float* x1 = x0 + 32 * HS;
        const float* x2 = x1 + 32 * HS;
        const float* wr = w3s + 4 * warp;
#pragma unroll 4
        for (int k = 0; k < 64; ++k) {
            ulonglong2 wA = *(const ulonglong2*)(wr);
            wr += 32;
            ull xp0 = pack2(x0[k]), xp1 = pack2(x1[k]), xp2 = pack2(x2[k]);
            acc[0][0] = ffma2(xp0, wA.x, acc[0][0]);
            acc[0][1] = ffma2(xp0, wA.y, acc[0][1]);
            acc[1][0] = ffma2(xp1, wA.x, acc[1][0]);
            acc[1][1] = ffma2(xp1, wA.y, acc[1][1]);
            acc[2][0] = ffma2(xp2, wA.x, acc[2][0]);
            acc[2][1] = ffma2(xp2, wA.y, acc[2][1]);
        }
        __syncthreads();   // all h2 reads done before Bt (h1) is overwritten with y
#pragma unroll
        for (int i = 0; i < 3; ++i) {
            float* od = Bt + (lane + 32 * i) * OS + 4 * warp;
#pragma unroll
            for (int p = 0; p < 2; ++p) {
                float lo, hi;
                unpack2(acc[i][p], lo, hi);
                od[2 * p]     = lo;
                od[2 * p + 1] = hi;
            }
        }
    }
    __syncthreads();

    // ---- coalesced output: Bt[bond][32] -> out (float4 per lane) ----
    {
        float4* out4 = (float4*)out;
#pragma unroll
        for (int it = 0; it < 3; ++it) {
            int idx = tid + it * THREADS;        // BM*8 = 768 items
            int b = idx >> 3, c = idx & 7;
            int g = gbase + b;
            if (g < n_bonds) {
                const float* s = Bt + b * OS + 4 * c;
                out4[(size_t)g * 8 + c] = make_float4(s[0], s[1], s[2], s[3]);
            }
        }
    }
}

extern "C" void kernel_launch(void* const* d_in, const int* in_sizes, int n_in,
                              void* d_out, int out_size) {
    const float* bonds = (const float*)d_in[0];
    const int*   ia1   = (const int*)  d_in[1];
    const int*   ia2   = (const int*)  d_in[2];
    const float* atoms = (const float*)d_in[3];
    const float* W1    = (const float*)d_in[4];
    const float* B1    = (const float*)d_in[5];
    const float* W2    = (const float*)d_in[6];
    const float* B2    = (const float*)d_in[7];
    const float* W3    = (const float*)d_in[8];
    const float* B3    = (const float*)d_in[9];
    float*       out   = (float*)d_out;

    const int n_bonds = in_sizes[1];

    cudaFuncSetAttribute(edge_mlp_kernel,
                         cudaFuncAttributeMaxDynamicSharedMemorySize,
                         (int)SMEM_BYTES);

    const int grid = (n_bonds + BM - 1) / BM;
    edge_mlp_kernel<<<grid, THREADS, SMEM_BYTES>>>(bonds, ia1, ia2, atoms,
                                                   W1, B1, W2, B2, W3, B3,
                                                   out, n_bonds);
}

// round 10
// speedup vs baseline: 2.2791x; 1.5366x over previous
#include <cuda_runtime.h>
#include <cuda_bf16.h>
#include <cstdint>

#define RRELU_SLOPE 0.22916666666666666f

static constexpr int TB = 256;          // 8 warps
static constexpr int BM = 128;          // bonds per CTA (one 16-row m-tile per warp)

// ---- smem layout (bytes) ----
static constexpr uint32_t OFF_IDX1 = 0;        // 128 int
static constexpr uint32_t OFF_IDX2 = 512;      // 128 int
static constexpr uint32_t OFF_B1S  = 1024;     // 64 f32
static constexpr uint32_t OFF_B2S  = 1280;     // 64 f32
static constexpr uint32_t OFF_B3S  = 1536;     // 32 f32
static constexpr uint32_t OFF_A    = 2048;     // bf16 [128][ASTR]: x hi(0-95)|lo(96-191); reused as h tiles
static constexpr int      ASTR     = 200;      // 400B ≡ 16 mod 128 -> conflict-free ldmatrix
static constexpr uint32_t OFF_W1   = OFF_A  + 128 * ASTR * 2;     // bf16 [192][W12STR]: Wh(0-95)|Wl(96-191)
static constexpr int      W12STR   = 72;       // 144B ≡ 16 mod 128
static constexpr uint32_t OFF_W2   = OFF_W1 + 192 * W12STR * 2;   // bf16 [128][W12STR]
static constexpr uint32_t OFF_W3   = OFF_W2 + 128 * W12STR * 2;   // bf16 [128][W3STR]
static constexpr int      W3STR    = 40;       // 80B step -> disjoint 16B chunks
static constexpr uint32_t SMEM_BYTES = OFF_W3 + 128 * W3STR * 2;  // 109568 B -> 2 CTAs/SM

// ---- warp-level primitives (plain-PTX, valid on .target sm_103) ----
__device__ __forceinline__ uint32_t smem_u32(const void* p) {
    uint32_t a;
    asm("{ .reg .u64 t; cvta.to.shared.u64 t, %1; cvt.u32.u64 %0, t; }" : "=r"(a) : "l"(p));
    return a;
}
__device__ __forceinline__ void ldsm4(uint32_t (&r)[4], uint32_t a) {
    asm volatile("ldmatrix.sync.aligned.m8n8.x4.shared.b16 {%0,%1,%2,%3}, [%4];"
                 : "=r"(r[0]), "=r"(r[1]), "=r"(r[2]), "=r"(r[3]) : "r"(a));
}
__device__ __forceinline__ void ldsm4t(uint32_t (&r)[4], uint32_t a) {
    asm volatile("ldmatrix.sync.aligned.m8n8.x4.trans.shared.b16 {%0,%1,%2,%3}, [%4];"
                 : "=r"(r[0]), "=r"(r[1]), "=r"(r[2]), "=r"(r[3]) : "r"(a));
}
__device__ __forceinline__ void mma16816(float (&c)[4], const uint32_t (&a)[4],
                                         uint32_t b0, uint32_t b1) {
    asm volatile(
        "mma.sync.aligned.m16n8k16.row.col.f32.bf16.bf16.f32 "
        "{%0,%1,%2,%3}, {%4,%5,%6,%7}, {%8,%9}, {%0,%1,%2,%3};"
        : "+f"(c[0]), "+f"(c[1]), "+f"(c[2]), "+f"(c[3])
        : "r"(a[0]), "r"(a[1]), "r"(a[2]), "r"(a[3]), "r"(b0), "r"(b1));
}

__device__ __forceinline__ float rrelu(float v) { return (v >= 0.0f) ? v : v * RRELU_SLOPE; }

__device__ __forceinline__ void split_bf16(float f, uint16_t& h, uint16_t& l) {
    __nv_bfloat16 bh = __float2bfloat16(f);
    float r = f - __bfloat162float(bh);
    h = __bfloat16_as_ushort(bh);
    l = __bfloat16_as_ushort(__float2bfloat16(r));
}
__device__ __forceinline__ uint32_t pack_split_hi(float f0, float f1, uint32_t& lo) {
    uint16_t h0, l0, h1, l1;
    split_bf16(f0, h0, l0);
    split_bf16(f1, h1, l1);
    lo = (uint32_t)l0 | ((uint32_t)l1 << 16);
    return (uint32_t)h0 | ((uint32_t)h1 << 16);
}

__global__ void __launch_bounds__(TB, 2)
edge_mlp_hmma(const float* __restrict__ bonds,
              const int*   __restrict__ ia1,
              const int*   __restrict__ ia2,
              const float* __restrict__ atoms,
              const float* __restrict__ W1, const float* __restrict__ B1,
              const float* __restrict__ W2, const float* __restrict__ B2,
              const float* __restrict__ W3, const float* __restrict__ B3,
              float* __restrict__ out, int n_bonds) {
    extern __shared__ char smem[];
    const uint32_t sb = smem_u32(smem);
    const int tid  = threadIdx.x;
    const int lane = tid & 31;
    const int warp = tid >> 5;
    const int gid  = lane >> 2;           // row group 0..7
    const int tig  = lane & 3;            // thread-in-group
    const int gbase = blockIdx.x * BM;
    const int mrow  = 16 * warp;          // this warp's 16 rows

    int*   i1s = (int*)(smem + OFF_IDX1);
    int*   i2s = (int*)(smem + OFF_IDX2);
    float* b1s = (float*)(smem + OFF_B1S);
    float* b2s = (float*)(smem + OFF_B2S);
    float* b3s = (float*)(smem + OFF_B3S);

    // ---- stage 0: gather indices + biases ----
    if (tid < 128) {
        int g = gbase + tid;
        i1s[tid] = (g < n_bonds) ? ia1[g] : 0;
    } else {
        int t = tid - 128, g = gbase + t;
        i2s[t] = (g < n_bonds) ? ia2[g] : 0;
    }
    if (tid < 64) { b1s[tid] = B1[tid]; b2s[tid] = B2[tid]; }
    else if (tid < 96) { b3s[tid - 64] = B3[tid - 64]; }
    __syncthreads();

    // ---- stage 1: x -> A (hi|lo bf16), weights -> W tiles ([Wh;Wl], [K][N]) ----
    {
        const float4* atoms4 = (const float4*)atoms;
        const float4* bonds4 = (const float4*)bonds;
#pragma unroll
        for (int it = 0; it < 12; ++it) {             // 128 rows x 24 float4
            int i = tid + it * TB;
            int m = i / 24, c4 = i % 24;
            float4 v; int k0;
            if (c4 < 8)       { v = atoms4[(size_t)i1s[m] * 8 + c4];       k0 = 4 * c4; }
            else if (c4 < 16) { v = atoms4[(size_t)i2s[m] * 8 + (c4 - 8)]; k0 = 32 + 4 * (c4 - 8); }
            else { int g = gbase + m; if (g >= n_bonds) g = gbase;
                   v = bonds4[(size_t)g * 8 + (c4 - 16)];                  k0 = 64 + 4 * (c4 - 16); }
            uint32_t l0, l1;
            uint32_t h0 = pack_split_hi(v.x, v.y, l0);
            uint32_t h1 = pack_split_hi(v.z, v.w, l1);
            char* rowp = smem + OFF_A + (size_t)m * (ASTR * 2);
            *(uint2*)(rowp + 2 * k0)        = make_uint2(h0, h1);
            *(uint2*)(rowp + 2 * (96 + k0)) = make_uint2(l0, l1);
        }
#pragma unroll
        for (int it = 0; it < 24; ++it) {             // W1 [96][64]
            int i = tid + it * TB;
            int k = i >> 6, n = i & 63;
            uint16_t h, l; split_bf16(W1[i], h, l);
            *(uint16_t*)(smem + OFF_W1 + ((size_t)k * W12STR + n) * 2)        = h;
            *(uint16_t*)(smem + OFF_W1 + ((size_t)(96 + k) * W12STR + n) * 2) = l;
        }
#pragma unroll
        for (int it = 0; it < 16; ++it) {             // W2 [64][64]
            int i = tid + it * TB;
            int k = i >> 6, n = i & 63;
            uint16_t h, l; split_bf16(W2[i], h, l);
            *(uint16_t*)(smem + OFF_W2 + ((size_t)k * W12STR + n) * 2)        = h;
            *(uint16_t*)(smem + OFF_W2 + ((size_t)(64 + k) * W12STR + n) * 2) = l;
        }
#pragma unroll
        for (int it = 0; it < 8; ++it) {              // W3 [64][32]
            int i = tid + it * TB;
            int k = i >> 5, n = i & 31;
            uint16_t h, l; split_bf16(W3[i], h, l);
            *(uint16_t*)(smem + OFF_W3 + ((size_t)k * W3STR + n) * 2)        = h;
            *(uint16_t*)(smem + OFF_W3 + ((size_t)(64 + k) * W3STR + n) * 2) = l;
        }
    }
    __syncthreads();
    // From here every warp touches ONLY its 16 rows of A -> no more barriers.

    // ldmatrix lane address components
    const uint32_t aBase = sb + OFF_A +
        ((uint32_t)(mrow + (lane & 15)) * ASTR + 8u * (uint32_t)(lane >> 4)) * 2u;
    const uint32_t bRow = (uint32_t)((lane & 7) + 8 * ((lane >> 3) & 1));   // k-row within step
    const uint32_t bCol = 8u * (uint32_t)(lane >> 4);                        // +8 for 2nd n-tile

    // h-store base for epilogues: rows mrow+gid / mrow+gid+8
    char* hRow0 = smem + OFF_A + (size_t)(mrow + gid) * (ASTR * 2);
    char* hRow8 = hRow0 + 8 * (ASTR * 2);

    // ---------------- layer 1: x[96] -> h1[64] ----------------
    {
        float acc[8][4];
#pragma unroll
        for (int j = 0; j < 8; ++j) {
            float be = b1s[8 * j + 2 * tig], bo = b1s[8 * j + 2 * tig + 1];
            acc[j][0] = be; acc[j][1] = bo; acc[j][2] = be; acc[j][3] = bo;
        }
#pragma unroll
        for (int t = 0; t < 3; ++t) {
            const int ab = (t == 1) ? 96 : 0;           // A col base (hi/lo)
            const int wb = (t == 2) ? 96 : 0;           // W row base (hi/lo)
#pragma unroll
            for (int s = 0; s < 6; ++s) {
                uint32_t a[4];
                ldsm4(a, aBase + (uint32_t)(ab + 16 * s) * 2u);
                uint32_t wb_addr = sb + OFF_W1 +
                    ((uint32_t)(wb + 16 * s) + bRow) * (W12STR * 2u) + bCol * 2u;
#pragma unroll
                for (int jg = 0; jg < 4; ++jg) {
                    uint32_t b[4];
                    ldsm4t(b, wb_addr + (uint32_t)(16 * jg) * 2u);
                    mma16816(acc[2 * jg],     a, b[0], b[1]);
                    mma16816(acc[2 * jg + 1], a, b[2], b[3]);
                }
            }
        }
        // epilogue: bias done; rrelu + split -> h1 (hi cols 0-63, lo 64-127), in place
#pragma unroll
        for (int j = 0; j < 8; ++j) {
            int col = 8 * j + 2 * tig;
            uint32_t lo0, lo8;
            uint32_t hi0 = pack_split_hi(rrelu(acc[j][0]), rrelu(acc[j][1]), lo0);
            uint32_t hi8 = pack_split_hi(rrelu(acc[j][2]), rrelu(acc[j][3]), lo8);
            *(uint32_t*)(hRow0 + 2 * col)        = hi0;
            *(uint32_t*)(hRow0 + 2 * (64 + col)) = lo0;
            *(uint32_t*)(hRow8 + 2 * col)        = hi8;
            *(uint32_t*)(hRow8 + 2 * (64 + col)) = lo8;
        }
    }
    __syncwarp();

    // ---------------- layer 2: h1[64] -> h2[64] ----------------
    {
        float acc[8][4];
#pragma unroll
        for (int j = 0; j < 8; ++j) {
            float be = b2s[8 * j + 2 * tig], bo = b2s[8 * j + 2 * tig + 1];
            acc[j][0] = be; acc[j][1] = bo; acc[j][2] = be; acc[j][3] = bo;
        }
#pragma unroll
        for (int t = 0; t < 3; ++t) {
            const int ab = (t == 1) ? 64 : 0;
            const int wb = (t == 2) ? 64 : 0;
#pragma unroll
            for (int s = 0; s < 4; ++s) {
                uint32_t a[4];
                ldsm4(a, aBase + (uint32_t)(ab + 16 * s) * 2u);
                uint32_t wb_addr = sb + OFF_W2 +
                    ((uint32_t)(wb + 16 * s) + bRow) * (W12STR * 2u) + bCol * 2u;
#pragma unroll
                for (int jg = 0; jg < 4; ++jg) {
                    uint32_t b[4];
                    ldsm4t(b, wb_addr + (uint32_t)(16 * jg) * 2u);
                    mma16816(acc[2 * jg],     a, b[0], b[1]);
                    mma16816(acc[2 * jg + 1], a, b[2], b[3]);
                }
            }
        }
#pragma unroll
        for (int j = 0; j < 8; ++j) {
            int col = 8 * j + 2 * tig;
            uint32_t lo0, lo8;
            uint32_t hi0 = pack_split_hi(rrelu(acc[j][0]), rrelu(acc[j][1]), lo0);
            uint32_t hi8 = pack_split_hi(rrelu(acc[j][2]), rrelu(acc[j][3]), lo8);
            *(uint32_t*)(hRow0 + 2 * col)        = hi0;
            *(uint32_t*)(hRow0 + 2 * (64 + col)) = lo0;
            *(uint32_t*)(hRow8 + 2 * col)        = hi8;
            *(uint32_t*)(hRow8 + 2 * (64 + col)) = lo8;
        }
    }
    __syncwarp();

    // ---------------- layer 3: h2[64] -> y[32], direct store ----------------
    {
        float acc[4][4];
#pragma unroll
        for (int j = 0; j < 4; ++j) {
            float be = b3s[8 * j + 2 * tig], bo = b3s[8 * j + 2 * tig + 1];
            acc[j][0] = be; acc[j][1] = bo; acc[j][2] = be; acc[j][3] = bo;
        }
#pragma unroll
        for (int t = 0; t < 3; ++t) {
            const int ab = (t == 1) ? 64 : 0;
            const int wb = (t == 2) ? 64 : 0;
#pragma unroll
            for (int s = 0; s < 4; ++s) {
                uint32_t a[4];
                ldsm4(a, aBase + (uint32_t)(ab + 16 * s) * 2u);
                uint32_t wb_addr = sb + OFF_W3 +
                    ((uint32_t)(wb + 16 * s) + bRow) * (W3STR * 2u) + bCol * 2u;
#pragma unroll
                for (int jg = 0; jg < 2; ++jg) {
                    uint32_t b[4];
                    ldsm4t(b, wb_addr + (uint32_t)(16 * jg) * 2u);
                    mma16816(acc[2 * jg],     a, b[0], b[1]);
                    mma16816(acc[2 * jg + 1], a, b[2], b[3]);
                }
            }
        }
        int g0 = gbase + mrow + gid;
#pragma unroll
        for (int j = 0; j < 4; ++j) {
            int col = 8 * j + 2 * tig;
            if (g0 < n_bonds)
                *(float2*)(out + (size_t)g0 * 32 + col) =
                    make_float2(acc[j][0], acc[j][1]);
            if (g0 + 8 < n_bonds)
                *(float2*)(out + (size_t)(g0 + 8) * 32 + col) =
                    make_float2(acc[j][2], acc[j][3]);
        }
    }
}

extern "C" void kernel_launch(void* const* d_in, const int* in_sizes, int n_in,
                              void* d_out, int out_size) {
    const float* bonds = (const float*)d_in[0];
    const int*   ia1   = (const int*)  d_in[1];
    const int*   ia2   = (const int*)  d_in[2];
    const float* atoms = (const float*)d_in[3];
    const float* W1    = (const float*)d_in[4];
    const float* B1    = (const float*)d_in[5];
    const float* W2    = (const float*)d_in[6];
    const float* B2    = (const float*)d_in[7];
    const float* W3    = (const float*)d_in[8];
    const float* B3    = (const float*)d_in[9];
    float*       out   = (float*)d_out;

    const int n_bonds = in_sizes[1];

    cudaFuncSetAttribute(edge_mlp_hmma,
                         cudaFuncAttributeMaxDynamicSharedMemorySize,
                         (int)SMEM_BYTES);

    const int grid = (n_bonds + BM - 1) / BM;
    edge_mlp_hmma<<<grid, TB, SMEM_BYTES>>>(bonds, ia1, ia2, atoms,
                                            W1, B1, W2, B2, W3, B3,
                                            out, n_bonds);
}

// round 13
// speedup vs baseline: 3.9374x; 1.7276x over previous
#include <cuda_runtime.h>
#include <cuda_bf16.h>
#include <cstdint>

#define RRELU_SLOPE 0.22916666666666666f

static constexpr int TB = 256;          // 8 warps
static constexpr int BM = 128;          // bonds per CTA, 16 rows per warp
static constexpr int N_ATOMS_MAX = 50000;

// ---- device-global precomputed buffers (static alloc; no cudaMalloc) ----
__device__ __nv_bfloat16 g_atoms_sp[(size_t)N_ATOMS_MAX * 64];  // per row: hi[32] | lo[32]
__device__ uint4 g_wt4[3520];   // 56320B: W1t[192][72] | W2t[128][72] | W3t[128][40] bf16

// bf16-element offsets of the 3 tiles inside g_wt4
static constexpr int WT_W1 = 0;
static constexpr int WT_W2 = 13824;     // 192*72
static constexpr int WT_W3 = 23040;     // + 128*72

// ---- smem layout (bytes) ----
static constexpr uint32_t OFF_IDX1 = 0;        // 128 int
static constexpr uint32_t OFF_IDX2 = 512;
static constexpr uint32_t OFF_B1S  = 1024;     // 64 f32
static constexpr uint32_t OFF_B2S  = 1280;
static constexpr uint32_t OFF_B3S  = 1536;     // 32 f32
static constexpr uint32_t OFF_A    = 2048;     // bf16 [128][200]: x hi(0-95) | lo(96-191)
static constexpr int      ASTR     = 200;      // 400B row ≡ 16 mod 128 -> conflict-free ldmatrix
static constexpr uint32_t OFF_WT   = 2048 + 128 * ASTR * 2;            // 53248
static constexpr uint32_t OFF_W1T  = OFF_WT + WT_W1 * 2;               // rows stride 144B
static constexpr uint32_t OFF_W2T  = OFF_WT + WT_W2 * 2;               // 80896
static constexpr uint32_t OFF_W3T  = OFF_WT + WT_W3 * 2;               // 99328, stride 80B
static constexpr uint32_t SMEM_BYTES = OFF_WT + 56320;                 // 109568 -> 2 CTAs/SM

// ---- primitives (plain PTX, valid on .target sm_103) ----
__device__ __forceinline__ uint32_t smem_u32(const void* p) {
    uint32_t a;
    asm("{ .reg .u64 t; cvta.to.shared.u64 t, %1; cvt.u32.u64 %0, t; }" : "=r"(a) : "l"(p));
    return a;
}
__device__ __forceinline__ void ldsm4(uint32_t (&r)[4], uint32_t a) {
    asm volatile("ldmatrix.sync.aligned.m8n8.x4.shared.b16 {%0,%1,%2,%3}, [%4];"
                 : "=r"(r[0]), "=r"(r[1]), "=r"(r[2]), "=r"(r[3]) : "r"(a));
}
__device__ __forceinline__ void ldsm4t(uint32_t (&r)[4], uint32_t a) {
    asm volatile("ldmatrix.sync.aligned.m8n8.x4.trans.shared.b16 {%0,%1,%2,%3}, [%4];"
                 : "=r"(r[0]), "=r"(r[1]), "=r"(r[2]), "=r"(r[3]) : "r"(a));
}
__device__ __forceinline__ void mma16816(float (&c)[4], const uint32_t (&a)[4],
                                         uint32_t b0, uint32_t b1) {
    asm volatile(
        "mma.sync.aligned.m16n8k16.row.col.f32.bf16.bf16.f32 "
        "{%0,%1,%2,%3}, {%4,%5,%6,%7}, {%8,%9}, {%0,%1,%2,%3};"
        : "+f"(c[0]), "+f"(c[1]), "+f"(c[2]), "+f"(c[3])
        : "r"(a[0]), "r"(a[1]), "r"(a[2]), "r"(a[3]), "r"(b0), "r"(b1));
}

// rrelu via fixed-latency min/max (no predicate chain)
__device__ __forceinline__ float rrelu(float v) {
    return fmaxf(v, 0.0f) + RRELU_SLOPE * fminf(v, 0.0f);
}

// split pair (f0->low lane, f1->high lane): hi bf16x2 returned, lo bf16x2 out.
__device__ __forceinline__ uint32_t split2(float f0, float f1, uint32_t& lo) {
    uint32_t h;
    asm("cvt.rn.bf16x2.f32 %0, %1, %2;" : "=r"(h) : "f"(f1), "f"(f0));
    float g0 = __uint_as_float(h << 16);
    float g1 = __uint_as_float(h & 0xffff0000u);
    asm("cvt.rn.bf16x2.f32 %0, %1, %2;" : "=r"(lo) : "f"(f1 - g1), "f"(f0 - g0));
    return h;
}
__device__ __forceinline__ void splitfs(float f, uint16_t& h, uint16_t& l) {
    __nv_bfloat16 bh = __float2bfloat16(f);
    float r = f - __bfloat162float(bh);
    h = __bfloat16_as_ushort(bh);
    l = __bfloat16_as_ushort(__float2bfloat16(r));
}

// ---- precompute kernel A: split atoms into [hi32|lo32] bf16 rows ----
__global__ void split_atoms_k(const float* __restrict__ atoms, int n_items) {
    int id = blockIdx.x * blockDim.x + threadIdx.x;   // n_atoms * 8 items
    if (id >= n_items) return;
    float4 v = ((const float4*)atoms)[id];
    int row = id >> 3, q = id & 7;
    uint32_t l0, l1;
    uint32_t h0 = split2(v.x, v.y, l0);
    uint32_t h1 = split2(v.z, v.w, l1);
    uint2* base = (uint2*)(g_atoms_sp + (size_t)row * 64);
    base[q]     = make_uint2(h0, h1);
    base[8 + q] = make_uint2(l0, l1);
}

// ---- precompute kernel B: split+relayout weights into smem-tile image ----
__global__ void split_weights_k(const float* __restrict__ W1,
                                const float* __restrict__ W2,
                                const float* __restrict__ W3) {
    int i = blockIdx.x * blockDim.x + threadIdx.x;
    uint16_t* wt = (uint16_t*)g_wt4;
    if (i < 6144) {                       // W1 [96][64] -> [192][72]
        int k = i >> 6, n = i & 63;
        uint16_t h, l; splitfs(W1[i], h, l);
        wt[WT_W1 + k * 72 + n]        = h;
        wt[WT_W1 + (96 + k) * 72 + n] = l;
    } else if (i < 10240) {               // W2 [64][64] -> [128][72]
        int j = i - 6144, k = j >> 6, n = j & 63;
        uint16_t h, l; splitfs(W2[j], h, l);
        wt[WT_W2 + k * 72 + n]        = h;
        wt[WT_W2 + (64 + k) * 72 + n] = l;
    } else if (i < 12288) {               // W3 [64][32] -> [128][40]
        int j = i - 10240, k = j >> 5, n = j & 31;
        uint16_t h, l; splitfs(W3[j], h, l);
        wt[WT_W3 + k * 40 + n]        = h;
        wt[WT_W3 + (64 + k) * 40 + n] = l;
    }
}

// ---- main kernel ----
__global__ void __launch_bounds__(TB, 2)
edge_mlp_hmma2(const float* __restrict__ bonds,
               const int*   __restrict__ ia1,
               const int*   __restrict__ ia2,
               const float* __restrict__ B1,
               const float* __restrict__ B2,
               const float* __restrict__ B3,
               float* __restrict__ out, int n_bonds) {
    extern __shared__ char smem[];
    const uint32_t sb = smem_u32(smem);
    const int tid  = threadIdx.x;
    const int lane = tid & 31;
    const int warp = tid >> 5;
    const int gid  = lane >> 2;
    const int tig  = lane & 3;
    const int gbase = blockIdx.x * BM;
    const int mrow  = 16 * warp;

    int*   i1s = (int*)(smem + OFF_IDX1);
    int*   i2s = (int*)(smem + OFF_IDX2);
    float* b1s = (float*)(smem + OFF_B1S);
    float* b2s = (float*)(smem + OFF_B2S);
    float* b3s = (float*)(smem + OFF_B3S);

    // stage 0: indices + biases
    if (tid < 128) {
        int g = gbase + tid;
        i1s[tid] = (g < n_bonds) ? ia1[g] : 0;
    } else {
        int t = tid - 128, g = gbase + t;
        i2s[t] = (g < n_bonds) ? ia2[g] : 0;
    }
    if (tid < 64) { b1s[tid] = B1[tid]; b2s[tid] = B2[tid]; }
    else if (tid < 96) { b3s[tid - 64] = B3[tid - 64]; }
    __syncthreads();

    // stage 1a: weight tile image (straight int4 copies)
#pragma unroll
    for (int it = 0; it < 14; ++it) {
        int i = tid + it * TB;
        if (i < 3520) *(uint4*)(smem + OFF_WT + 16 * i) = g_wt4[i];
    }
    // stage 1b: atom halves (raw 16B copies from pre-split table)
#pragma unroll
    for (int it = 0; it < 8; ++it) {
        int id = tid + it * TB;                 // 128 rows x 16 chunks
        int m = id >> 4, c = id & 15;
        int aidx = (c < 8) ? i1s[m] : i2s[m];
        const uint4 v = *(const uint4*)((const char*)g_atoms_sp + (size_t)aidx * 128 + 16 * (c & 7));
        int base = (c < 4) ? 0 : (c < 8) ? 192 : (c < 12) ? 64 : 256;
        *(uint4*)(smem + OFF_A + (size_t)m * 400 + base + 16 * (c & 3)) = v;
    }
    // stage 1c: bond features, split in-kernel
#pragma unroll
    for (int it = 0; it < 4; ++it) {
        int id = tid + it * TB;                 // 128 rows x 8 float4
        int m = id >> 3, q = id & 7;
        int g = gbase + m;
        if (g >= n_bonds) g = gbase;
        float4 v = ((const float4*)bonds)[(size_t)g * 8 + q];
        uint32_t l0, l1;
        uint32_t h0 = split2(v.x, v.y, l0);
        uint32_t h1 = split2(v.z, v.w, l1);
        char* rowp = smem + OFF_A + (size_t)m * 400;
        *(uint2*)(rowp + 128 + 8 * q) = make_uint2(h0, h1);   // hi cols 64..95
        *(uint2*)(rowp + 320 + 8 * q) = make_uint2(l0, l1);   // lo cols 160..191
    }
    __syncthreads();

    // ldmatrix lane addressing
    const uint32_t aBase = sb + OFF_A +
        (uint32_t)(mrow + (lane & 15)) * 400u + 16u * (uint32_t)(lane >> 4);
    const uint32_t bRow = (uint32_t)((lane & 7) + 8 * ((lane >> 3) & 1));
    const uint32_t bCol = 8u * (uint32_t)(lane >> 4);
    const uint32_t w1b = sb + OFF_W1T + bRow * 144u + bCol * 2u;
    const uint32_t w2b = sb + OFF_W2T + bRow * 144u + bCol * 2u;
    const uint32_t w3b = sb + OFF_W3T + bRow * 80u  + bCol * 2u;

    // ---------------- layer 1: x[96] -> h1[64] ----------------
    float acc1[8][4];
#pragma unroll
    for (int j = 0; j < 8; ++j) {
        float be = b1s[8 * j + 2 * tig], bo = b1s[8 * j + 2 * tig + 1];
        acc1[j][0] = be; acc1[j][1] = bo; acc1[j][2] = be; acc1[j][3] = bo;
    }
#pragma unroll
    for (int s = 0; s < 6; ++s) {
        uint32_t aH[4], aL[4];
        ldsm4(aH, aBase + 32u * s);              // hi cols 16s
        ldsm4(aL, aBase + 192u + 32u * s);       // lo cols 96+16s
#pragma unroll
        for (int jg = 0; jg < 4; ++jg) {
            uint32_t bH[4], bL[4];
            ldsm4t(bH, w1b + (16u * s) * 144u + 32u * jg);
            ldsm4t(bL, w1b + (96u + 16u * s) * 144u + 32u * jg);
            mma16816(acc1[2 * jg],     aH, bH[0], bH[1]);
            mma16816(acc1[2 * jg + 1], aH, bH[2], bH[3]);
            mma16816(acc1[2 * jg],     aL, bH[0], bH[1]);
            mma16816(acc1[2 * jg + 1], aL, bH[2], bH[3]);
            mma16816(acc1[2 * jg],     aH, bL[0], bL[1]);
            mma16816(acc1[2 * jg + 1], aH, bL[2], bL[3]);
        }
    }
    // register epilogue: C-frags of tiles (2s,2s+1) ARE the A-frags of k-step s
    uint32_t aH2[4][4], aL2[4][4];
#pragma unroll
    for (int s = 0; s < 4; ++s) {
        aH2[s][0] = split2(rrelu(acc1[2*s][0]),   rrelu(acc1[2*s][1]),   aL2[s][0]);
        aH2[s][1] = split2(rrelu(acc1[2*s][2]),   rrelu(acc1[2*s][3]),   aL2[s][1]);
        aH2[s][2] = split2(rrelu(acc1[2*s+1][0]), rrelu(acc1[2*s+1][1]), aL2[s][2]);
        aH2[s][3] = split2(rrelu(acc1[2*s+1][2]), rrelu(acc1[2*s+1][3]), aL2[s][3]);
    }

    // ---------------- layer 2: h1[64] -> h2[64] (A in registers) ----------------
    float acc2[8][4];
#pragma unroll
    for (int j = 0; j < 8; ++j) {
        float be = b2s[8 * j + 2 * tig], bo = b2s[8 * j + 2 * tig + 1];
        acc2[j][0] = be; acc2[j][1] = bo; acc2[j][2] = be; acc2[j][3] = bo;
    }
#pragma unroll
    for (int s = 0; s < 4; ++s) {
#pragma unroll
        for (int jg = 0; jg < 4; ++jg) {
            uint32_t bH[4], bL[4];
            ldsm4t(bH, w2b + (16u * s) * 144u + 32u * jg);
            ldsm4t(bL, w2b + (64u + 16u * s) * 144u + 32u * jg);
            mma16816(acc2[2 * jg],     aH2[s], bH[0], bH[1]);
            mma16816(acc2[2 * jg + 1], aH2[s], bH[2], bH[3]);
            mma16816(acc2[2 * jg],     aL2[s], bH[0], bH[1]);
            mma16816(acc2[2 * jg + 1], aL2[s], bH[2], bH[3]);
            mma16816(acc2[2 * jg],     aH2[s], bL[0], bL[1]);
            mma16816(acc2[2 * jg + 1], aH2[s], bL[2], bL[3]);
        }
    }
    uint32_t aH3[4][4], aL3[4][4];
#pragma unroll
    for (int s = 0; s < 4; ++s) {
        aH3[s][0] = split2(rrelu(acc2[2*s][0]),   rrelu(acc2[2*s][1]),   aL3[s][0]);
        aH3[s][1] = split2(rrelu(acc2[2*s][2]),   rrelu(acc2[2*s][3]),   aL3[s][1]);
        aH3[s][2] = split2(rrelu(acc2[2*s+1][0]), rrelu(acc2[2*s+1][1]), aL3[s][2]);
        aH3[s][3] = split2(rrelu(acc2[2*s+1][2]), rrelu(acc2[2*s+1][3]), aL3[s][3]);
    }

    // ---------------- layer 3: h2[64] -> y[32] ----------------
    float acc3[4][4];
#pragma unroll
    for (int j = 0; j < 4; ++j) {
        float be = b3s[8 * j + 2 * tig], bo = b3s[8 * j + 2 * tig + 1];
        acc3[j][0] = be; acc3[j][1] = bo; acc3[j][2] = be; acc3[j][3] = bo;
    }
#pragma unroll
    for (int s = 0; s < 4; ++s) {
#pragma unroll
        for (int jg = 0; jg < 2; ++jg) {
            uint32_t bH[4], bL[4];
            ldsm4t(bH, w3b + (16u * s) * 80u + 32u * jg);
            ldsm4t(bL, w3b + (64u + 16u * s) * 80u + 32u * jg);
            mma16816(acc3[2 * jg],     aH3[s], bH[0], bH[1]);
            mma16816(acc3[2 * jg + 1], aH3[s], bH[2], bH[3]);
            mma16816(acc3[2 * jg],     aL3[s], bH[0], bH[1]);
            mma16816(acc3[2 * jg + 1], aL3[s], bH[2], bH[3]);
            mma16816(acc3[2 * jg],     aH3[s], bL[0], bL[1]);
            mma16816(acc3[2 * jg + 1], aH3[s], bL[2], bL[3]);
        }
    }
    // direct store
    {
        int g0 = gbase + mrow + gid;
#pragma unroll
        for (int j = 0; j < 4; ++j) {
            int col = 8 * j + 2 * tig;
            if (g0 < n_bonds)
                *(float2*)(out + (size_t)g0 * 32 + col) = make_float2(acc3[j][0], acc3[j][1]);
            if (g0 + 8 < n_bonds)
                *(float2*)(out + (size_t)(g0 + 8) * 32 + col) = make_float2(acc3[j][2], acc3[j][3]);
        }
    }
}

extern "C" void kernel_launch(void* const* d_in, const int* in_sizes, int n_in,
                              void* d_out, int out_size) {
    const float* bonds = (const float*)d_in[0];
    const int*   ia1   = (const int*)  d_in[1];
    const int*   ia2   = (const int*)  d_in[2];
    const float* atoms = (const float*)d_in[3];
    const float* W1    = (const float*)d_in[4];
    const float* B1    = (const float*)d_in[5];
    const float* W2    = (const float*)d_in[6];
    const float* B2    = (const float*)d_in[7];
    const float* W3    = (const float*)d_in[8];
    const float* B3    = (const float*)d_in[9];
    float*       out   = (float*)d_out;

    const int n_bonds = in_sizes[1];
    int n_atoms = in_sizes[3] / 32;
    if (n_atoms > N_ATOMS_MAX) n_atoms = N_ATOMS_MAX;

    // precompute: split atoms + weights (graph-capturable plain launches)
    const int aitems = n_atoms * 8;
    split_atoms_k<<<(aitems + 255) / 256, 256>>>(atoms, aitems);
    split_weights_k<<<48, 256>>>(W1, W2, W3);

    cudaFuncSetAttribute(edge_mlp_hmma2,
                         cudaFuncAttributeMaxDynamicSharedMemorySize,
                         (int)SMEM_BYTES);
    const int grid = (n_bonds + BM - 1) / BM;
    edge_mlp_hmma2<<<grid, TB, SMEM_BYTES>>>(bonds, ia1, ia2,
                                             B1, B2, B3, out, n_bonds);
}

// round 16
// speedup vs baseline: 4.5599x; 1.1581x over previous
#include <cuda_runtime.h>
#include <cuda_bf16.h>
#include <cstdint>

#define RRELU_SLOPE 0.22916666666666666f

static constexpr int TB = 256;          // 8 warps per CTA
static constexpr int GRID = 304;        // persistent: 2 CTAs/SM x 152 SMs
static constexpr int N_ATOMS_MAX = 50000;

// ---- device-global precomputed buffers (static alloc; no cudaMalloc) ----
__device__ __nv_bfloat16 g_atoms_sp[(size_t)N_ATOMS_MAX * 64];  // per row: hi[32] | lo[32]
__device__ uint4 g_wt4[3520];   // 56320B: W1t[192][72] | W2t[128][72] | W3t[128][40] bf16

static constexpr int WT_W1 = 0;
static constexpr int WT_W2 = 13824;     // 192*72
static constexpr int WT_W3 = 23040;     // + 128*72

// ---- smem layout (bytes) ----
static constexpr uint32_t OFF_B1S  = 0;        // 64 f32
static constexpr uint32_t OFF_B2S  = 256;
static constexpr uint32_t OFF_B3S  = 512;      // 32 f32
static constexpr uint32_t OFF_A    = 1024;     // bf16 [128][200]: per-warp 16 rows, hi(0-95)|lo(96-191)
static constexpr uint32_t OFF_WT   = OFF_A + 128 * 400;               // 52224
static constexpr uint32_t OFF_W1T  = OFF_WT + WT_W1 * 2;              // row stride 144B
static constexpr uint32_t OFF_W2T  = OFF_WT + WT_W2 * 2;
static constexpr uint32_t OFF_W3T  = OFF_WT + WT_W3 * 2;              // row stride 80B
static constexpr uint32_t SMEM_BYTES = OFF_WT + 56320;                // 108544 -> 2 CTAs/SM

// ---- primitives (plain PTX, valid on .target sm_103) ----
__device__ __forceinline__ uint32_t smem_u32(const void* p) {
    uint32_t a;
    asm("{ .reg .u64 t; cvta.to.shared.u64 t, %1; cvt.u32.u64 %0, t; }" : "=r"(a) : "l"(p));
    return a;
}
__device__ __forceinline__ void cpasync16(uint32_t dst, const void* src) {
    asm volatile("cp.async.cg.shared.global [%0], [%1], 16;" :: "r"(dst), "l"(src));
}
__device__ __forceinline__ void ldsm4(uint32_t (&r)[4], uint32_t a) {
    asm volatile("ldmatrix.sync.aligned.m8n8.x4.shared.b16 {%0,%1,%2,%3}, [%4];"
                 : "=r"(r[0]), "=r"(r[1]), "=r"(r[2]), "=r"(r[3]) : "r"(a));
}
__device__ __forceinline__ void ldsm4t(uint32_t (&r)[4], uint32_t a) {
    asm volatile("ldmatrix.sync.aligned.m8n8.x4.trans.shared.b16 {%0,%1,%2,%3}, [%4];"
                 : "=r"(r[0]), "=r"(r[1]), "=r"(r[2]), "=r"(r[3]) : "r"(a));
}
__device__ __forceinline__ void mma16816(float (&c)[4], const uint32_t (&a)[4],
                                         uint32_t b0, uint32_t b1) {
    asm volatile(
        "mma.sync.aligned.m16n8k16.row.col.f32.bf16.bf16.f32 "
        "{%0,%1,%2,%3}, {%4,%5,%6,%7}, {%8,%9}, {%0,%1,%2,%3};"
        : "+f"(c[0]), "+f"(c[1]), "+f"(c[2]), "+f"(c[3])
        : "r"(a[0]), "r"(a[1]), "r"(a[2]), "r"(a[3]), "r"(b0), "r"(b1));
}
__device__ __forceinline__ float rrelu(float v) {
    return fmaxf(v, 0.0f) + RRELU_SLOPE * fminf(v, 0.0f);
}
__device__ __forceinline__ uint32_t split2(float f0, float f1, uint32_t& lo) {
    uint32_t h;
    asm("cvt.rn.bf16x2.f32 %0, %1, %2;" : "=r"(h) : "f"(f1), "f"(f0));
    float g0 = __uint_as_float(h << 16);
    float g1 = __uint_as_float(h & 0xffff0000u);
    asm("cvt.rn.bf16x2.f32 %0, %1, %2;" : "=r"(lo) : "f"(f1 - g1), "f"(f0 - g0));
    return h;
}
__device__ __forceinline__ void splitfs(float f, uint16_t& h, uint16_t& l) {
    __nv_bfloat16 bh = __float2bfloat16(f);
    float r = f - __bfloat162float(bh);
    h = __bfloat16_as_ushort(bh);
    l = __bfloat16_as_ushort(__float2bfloat16(r));
}

// ---- precompute kernel A: split atoms into [hi32|lo32] bf16 rows ----
__global__ void split_atoms_k(const float* __restrict__ atoms, int n_items) {
    int id = blockIdx.x * blockDim.x + threadIdx.x;
    if (id >= n_items) return;
    float4 v = ((const float4*)atoms)[id];
    int row = id >> 3, q = id & 7;
    uint32_t l0, l1;
    uint32_t h0 = split2(v.x, v.y, l0);
    uint32_t h1 = split2(v.z, v.w, l1);
    uint2* base = (uint2*)(g_atoms_sp + (size_t)row * 64);
    base[q]     = make_uint2(h0, h1);
    base[8 + q] = make_uint2(l0, l1);
}

// ---- precompute kernel B: split+relayout weights into smem-tile image ----
__global__ void split_weights_k(const float* __restrict__ W1,
                                const float* __restrict__ W2,
                                const float* __restrict__ W3) {
    int i = blockIdx.x * blockDim.x + threadIdx.x;
    uint16_t* wt = (uint16_t*)g_wt4;
    if (i < 6144) {
        int k = i >> 6, n = i & 63;
        uint16_t h, l; splitfs(W1[i], h, l);
        wt[WT_W1 + k * 72 + n]        = h;
        wt[WT_W1 + (96 + k) * 72 + n] = l;
    } else if (i < 10240) {
        int j = i - 6144, k = j >> 6, n = j & 63;
        uint16_t h, l; splitfs(W2[j], h, l);
        wt[WT_W2 + k * 72 + n]        = h;
        wt[WT_W2 + (64 + k) * 72 + n] = l;
    } else if (i < 12288) {
        int j = i - 10240, k = j >> 5, n = j & 31;
        uint16_t h, l; splitfs(W3[j], h, l);
        wt[WT_W3 + k * 40 + n]        = h;
        wt[WT_W3 + (64 + k) * 40 + n] = l;
    }
}

// ---- main persistent kernel: warp-independent 16-bond tiles ----
__global__ void __launch_bounds__(TB, 2)
edge_mlp_hmma3(const float* __restrict__ bonds,
               const int*   __restrict__ ia1,
               const int*   __restrict__ ia2,
               const float* __restrict__ B1,
               const float* __restrict__ B2,
               const float* __restrict__ B3,
               float* __restrict__ out, int n_bonds) {
    extern __shared__ char smem[];
    const uint32_t sb = smem_u32(smem);
    const int tid  = threadIdx.x;
    const int lane = tid & 31;
    const int warp = tid >> 5;
    const int gid  = lane >> 2;
    const int tig  = lane & 3;
    const int mrow = 16 * warp;            // warp's private 16 A-rows

    float* b1s = (float*)(smem + OFF_B1S);
    float* b2s = (float*)(smem + OFF_B2S);
    float* b3s = (float*)(smem + OFF_B3S);

    // ---- one-time staging: weights (int4 image copy) + biases ----
#pragma unroll
    for (int it = 0; it < 14; ++it) {
        int i = tid + it * TB;
        if (i < 3520) *(uint4*)(smem + OFF_WT + 16 * i) = g_wt4[i];
    }
    if (tid < 64) { b1s[tid] = B1[tid]; b2s[tid] = B2[tid]; }
    else if (tid < 96) { b3s[tid - 64] = B3[tid - 64]; }
    __syncthreads();          // ONLY CTA-wide barrier in the kernel

    // lane addressing (constant across tiles)
    const uint32_t aBase = sb + OFF_A +
        (uint32_t)(mrow + (lane & 15)) * 400u + 16u * (uint32_t)(lane >> 4);
    const uint32_t bRow = (uint32_t)((lane & 7) + 8 * ((lane >> 3) & 1));
    const uint32_t bCol = 8u * (uint32_t)(lane >> 4);
    const uint32_t w1b = sb + OFF_W1T + bRow * 144u + bCol * 2u;
    const uint32_t w2b = sb + OFF_W2T + bRow * 144u + bCol * 2u;
    const uint32_t w3b = sb + OFF_W3T + bRow * 80u  + bCol * 2u;

    // gather lane assignment (constant)
    const int grow  = lane >> 1;            // 0..15
    const int ghalf = lane & 1;             // atom1 / atom2
    const uint32_t dstrow = sb + OFF_A + (uint32_t)(mrow + grow) * 400u;
    const uint32_t dHi = dstrow + 64u * (uint32_t)ghalf;           // atom hi cols
    const uint32_t dLo = dstrow + 192u + 64u * (uint32_t)ghalf;    // atom lo cols

    const int n_tiles = (n_bonds + 15) >> 4;

    for (int t = blockIdx.x * 8 + warp; t < n_tiles; t += GRID * 8) {
        const int g0 = t * 16;

        // ---- gather: atoms via cp.async (pre-split), bonds via split ----
        {
            int g = g0 + grow;
            if (g >= n_bonds) g = n_bonds - 1;
            int aidx = ghalf ? ia2[g] : ia1[g];
            const char* src = (const char*)g_atoms_sp + (size_t)aidx * 128;
#pragma unroll
            for (int c = 0; c < 4; ++c) {
                cpasync16(dHi + 16u * c, src + 16 * c);
                cpasync16(dLo + 16u * c, src + 64 + 16 * c);
            }
        }
#pragma unroll
        for (int p = 0; p < 4; ++p) {
            int item = lane + 32 * p;               // 16 rows x 8 q
            int row = item >> 3, q = item & 7;
            int g = g0 + row;
            if (g >= n_bonds) g = n_bonds - 1;
            float4 v = ((const float4*)bonds)[(size_t)g * 8 + q];
            uint32_t l0, l1;
            uint32_t h0 = split2(v.x, v.y, l0);
            uint32_t h1 = split2(v.z, v.w, l1);
            char* rowp = smem + OFF_A + (size_t)(mrow + row) * 400;
            *(uint2*)(rowp + 128 + 8 * q) = make_uint2(h0, h1);   // hi cols 64..95
            *(uint2*)(rowp + 320 + 8 * q) = make_uint2(l0, l1);   // lo cols 160..191
        }
        asm volatile("cp.async.commit_group;" ::: "memory");
        asm volatile("cp.async.wait_group 0;" ::: "memory");
        __syncwarp();

        // ---------------- layer 1: x[96] -> h1[64] ----------------
        float acc1[8][4];
#pragma unroll
        for (int j = 0; j < 8; ++j) {
            float be = b1s[8 * j + 2 * tig], bo = b1s[8 * j + 2 * tig + 1];
            acc1[j][0] = be; acc1[j][1] = bo; acc1[j][2] = be; acc1[j][3] = bo;
        }
#pragma unroll
        for (int s = 0; s < 6; ++s) {
            uint32_t aH[4], aL[4];
            ldsm4(aH, aBase + 32u * s);
            ldsm4(aL, aBase + 192u + 32u * s);
#pragma unroll
            for (int jg = 0; jg < 4; ++jg) {
                uint32_t bH[4], bL[4];
                ldsm4t(bH, w1b + (16u * s) * 144u + 32u * jg);
                ldsm4t(bL, w1b + (96u + 16u * s) * 144u + 32u * jg);
                mma16816(acc1[2 * jg],     aH, bH[0], bH[1]);
                mma16816(acc1[2 * jg + 1], aH, bH[2], bH[3]);
                mma16816(acc1[2 * jg],     aL, bH[0], bH[1]);
                mma16816(acc1[2 * jg + 1], aL, bH[2], bH[3]);
                mma16816(acc1[2 * jg],     aH, bL[0], bL[1]);
                mma16816(acc1[2 * jg + 1], aH, bL[2], bL[3]);
            }
        }
        // register chaining: C-frags (tiles 2s,2s+1) == A-frags of k-step s
        uint32_t aH2[4][4], aL2[4][4];
#pragma unroll
        for (int s = 0; s < 4; ++s) {
            aH2[s][0] = split2(rrelu(acc1[2*s][0]),   rrelu(acc1[2*s][1]),   aL2[s][0]);
            aH2[s][1] = split2(rrelu(acc1[2*s][2]),   rrelu(acc1[2*s][3]),   aL2[s][1]);
            aH2[s][2] = split2(rrelu(acc1[2*s+1][0]), rrelu(acc1[2*s+1][1]), aL2[s][2]);
            aH2[s][3] = split2(rrelu(acc1[2*s+1][2]), rrelu(acc1[2*s+1][3]), aL2[s][3]);
        }

        // ---------------- layer 2: h1[64] -> h2[64] ----------------
        float acc2[8][4];
#pragma unroll
        for (int j = 0; j < 8; ++j) {
            float be = b2s[8 * j + 2 * tig], bo = b2s[8 * j + 2 * tig + 1];
            acc2[j][0] = be; acc2[j][1] = bo; acc2[j][2] = be; acc2[j][3] = bo;
        }
#pragma unroll
        for (int s = 0; s < 4; ++s) {
#pragma unroll
            for (int jg = 0; jg < 4; ++jg) {
                uint32_t bH[4], bL[4];
                ldsm4t(bH, w2b + (16u * s) * 144u + 32u * jg);
                ldsm4t(bL, w2b + (64u + 16u * s) * 144u + 32u * jg);
                mma16816(acc2[2 * jg],     aH2[s], bH[0], bH[1]);
                mma16816(acc2[2 * jg + 1], aH2[s], bH[2], bH[3]);
                mma16816(acc2[2 * jg],     aL2[s], bH[0], bH[1]);
                mma16816(acc2[2 * jg + 1], aL2[s], bH[2], bH[3]);
                mma16816(acc2[2 * jg],     aH2[s], bL[0], bL[1]);
                mma16816(acc2[2 * jg + 1], aH2[s], bL[2], bL[3]);
            }
        }
        uint32_t aH3[4][4], aL3[4][4];
#pragma unroll
        for (int s = 0; s < 4; ++s) {
            aH3[s][0] = split2(rrelu(acc2[2*s][0]),   rrelu(acc2[2*s][1]),   aL3[s][0]);
            aH3[s][1] = split2(rrelu(acc2[2*s][2]),   rrelu(acc2[2*s][3]),   aL3[s][1]);
            aH3[s][2] = split2(rrelu(acc2[2*s+1][0]), rrelu(acc2[2*s+1][1]), aL3[s][2]);
            aH3[s][3] = split2(rrelu(acc2[2*s+1][2]), rrelu(acc2[2*s+1][3]), aL3[s][3]);
        }

        // ---------------- layer 3: h2[64] -> y[32] ----------------
        float acc3[4][4];
#pragma unroll
        for (int j = 0; j < 4; ++j) {
            float be = b3s[8 * j + 2 * tig], bo = b3s[8 * j + 2 * tig + 1];
            acc3[j][0] = be; acc3[j][1] = bo; acc3[j][2] = be; acc3[j][3] = bo;
        }
#pragma unroll
        for (int s = 0; s < 4; ++s) {
#pragma unroll
            for (int jg = 0; jg < 2; ++jg) {
                uint32_t bH[4], bL[4];
                ldsm4t(bH, w3b + (16u * s) * 80u + 32u * jg);
                ldsm4t(bL, w3b + (64u + 16u * s) * 80u + 32u * jg);
                mma16816(acc3[2 * jg],     aH3[s], bH[0], bH[1]);
                mma16816(acc3[2 * jg + 1], aH3[s], bH[2], bH[3]);
                mma16816(acc3[2 * jg],     aL3[s], bH[0], bH[1]);
                mma16816(acc3[2 * jg + 1], aL3[s], bH[2], bH[3]);
                mma16816(acc3[2 * jg],     aH3[s], bL[0], bL[1]);
                mma16816(acc3[2 * jg + 1], aH3[s], bL[2], bL[3]);
            }
        }
        // direct store
        {
            int gr = g0 + gid;
#pragma unroll
            for (int j = 0; j < 4; ++j) {
                int col = 8 * j + 2 * tig;
                if (gr < n_bonds)
                    *(float2*)(out + (size_t)gr * 32 + col) = make_float2(acc3[j][0], acc3[j][1]);
                if (gr + 8 < n_bonds)
                    *(float2*)(out + (size_t)(gr + 8) * 32 + col) = make_float2(acc3[j][2], acc3[j][3]);
            }
        }
    }
}

extern "C" void kernel_launch(void* const* d_in, const int* in_sizes, int n_in,
                              void* d_out, int out_size) {
    const float* bonds = (const float*)d_in[0];
    const int*   ia1   = (const int*)  d_in[1];
    const int*   ia2   = (const int*)  d_in[2];
    const float* atoms = (const float*)d_in[3];
    const float* W1    = (const float*)d_in[4];
    const float* B1    = (const float*)d_in[5];
    const float* W2    = (const float*)d_in[6];
    const float* B2    = (const float*)d_in[7];
    const float* W3    = (const float*)d_in[8];
    const float* B3    = (const float*)d_in[9];
    float*       out   = (float*)d_out;

    const int n_bonds = in_sizes[1];
    int n_atoms = in_sizes[3] / 32;
    if (n_atoms > N_ATOMS_MAX) n_atoms = N_ATOMS_MAX;

    const int aitems = n_atoms * 8;
    split_atoms_k<<<(aitems + 255) / 256, 256>>>(atoms, aitems);
    split_weights_k<<<48, 256>>>(W1, W2, W3);

    cudaFuncSetAttribute(edge_mlp_hmma3,
                         cudaFuncAttributeMaxDynamicSharedMemorySize,
                         (int)SMEM_BYTES);
    edge_mlp_hmma3<<<GRID, TB, SMEM_BYTES>>>(bonds, ia1, ia2,
                                             B1, B2, B3, out, n_bonds);
}